// round 2
// baseline (speedup 1.0000x reference)
#include <cuda_runtime.h>
#include <math.h>

#define E 2048
#define EXP30 9.357622968840175e-14f   /* expf(-30) */
#define NSLAB 37
#define SLAB 56

// ---------------- static scratch ----------------
__device__ float4 g_colv[6 * E];          // (e2, exp(e2), exp(.2 e2), -)
__device__ float4 g_rowv[6 * E];          // (e1, exp(e1), exp(.2 e1), -)
__device__ float4 g_row2[6 * E];          // (e1, P1/R, N1/R, exp(-30)/R)
__device__ float4 g_hA[6 * E];            // h0..h3
__device__ float2 g_hB[6 * E];            // h4,h5
__device__ float  g_part[(size_t)NSLAB * E * 36];
__device__ float  g_hcat[2 * E * 18];
__device__ float  g_XW[E * 32];
__device__ float  g_G1p[8 * E * 32];
__device__ float  g_YO1[E * 32];
__device__ float4 g_Z[E];

// ---------------- K1: per-node h, e1, e2, exp factors ----------------
__global__ void k1_prep(const float* __restrict__ x0, const float* __restrict__ x1,
                        const float* __restrict__ Wt1, const float* __restrict__ at1,
                        const float* __restrict__ Wt2, const float* __restrict__ at2)
{
    int c = blockIdx.y;                        // combo 0..5 (gat*3+head)
    int i = blockIdx.x * 256 + threadIdx.x;
    int g = c / 3, t = c % 3;
    __shared__ float sW[192];
    __shared__ float sa[12];
    const float* W = (g == 0 ? Wt1 : Wt2) + t * 192;
    const float* a = (g == 0 ? at1 : at2) + t * 12;
    if (threadIdx.x < 192) sW[threadIdx.x] = W[threadIdx.x];
    if (threadIdx.x < 12)  sa[threadIdx.x] = a[threadIdx.x];
    __syncthreads();

    const float* x = (g == 0 ? x0 : x1) + i * 32;   // batch 0
    float h[6] = {0.f, 0.f, 0.f, 0.f, 0.f, 0.f};
#pragma unroll
    for (int k = 0; k < 32; k++) {
        float xk = x[k];
#pragma unroll
        for (int d = 0; d < 6; d++) h[d] = fmaf(xk, sW[k * 6 + d], h[d]);
    }
    float e1 = 0.f, e2 = 0.f;
#pragma unroll
    for (int d = 0; d < 6; d++) {
        e1 = fmaf(h[d], sa[d], e1);
        e2 = fmaf(h[d], sa[6 + d], e2);
    }
    g_rowv[c * E + i] = make_float4(e1, __expf(e1), __expf(0.2f * e1), 0.f);
    g_colv[c * E + i] = make_float4(e2, __expf(e2), __expf(0.2f * e2), 0.f);
    g_hA[c * E + i]   = make_float4(h[0], h[1], h[2], h[3]);
    g_hB[c * E + i]   = make_float2(h[4], h[5]);
}

// ---------------- K2: softmax row denominators ----------------
__global__ void __launch_bounds__(128) k2_rowsum(const float* __restrict__ adj)
{
    int warp = threadIdx.x >> 5, lane = threadIdx.x & 31;
    int r0 = blockIdx.x * 16 + warp * 4;

    float e1[4][6], P1[4][6], N1[4][6], acc[4][6], cnt[4];
#pragma unroll
    for (int r = 0; r < 4; r++) {
        cnt[r] = 0.f;
#pragma unroll
        for (int c = 0; c < 6; c++) {
            float4 v = g_rowv[c * E + r0 + r];
            e1[r][c] = v.x; P1[r][c] = v.y; N1[r][c] = v.z;
            acc[r][c] = 0.f;
        }
    }

    for (int k = 0; k < 16; k++) {
        int j = k * 128 + lane * 4;
        float4 av[4];
#pragma unroll
        for (int r = 0; r < 4; r++) {
            av[r] = *(const float4*)&adj[(size_t)(r0 + r) * E + j];
            cnt[r] += av[r].x + av[r].y + av[r].z + av[r].w;
        }
#pragma unroll
        for (int c = 0; c < 6; c++) {
            float4 cv[4];
            cv[0] = g_colv[c * E + j + 0];
            cv[1] = g_colv[c * E + j + 1];
            cv[2] = g_colv[c * E + j + 2];
            cv[3] = g_colv[c * E + j + 3];
#pragma unroll
            for (int r = 0; r < 4; r++) {
                const float* af = (const float*)&av[r];
#pragma unroll
                for (int q = 0; q < 4; q++) {
                    float x = e1[r][c] + cv[q].x;
                    float s = (x > 0.f ? P1[r][c] : N1[r][c]) *
                              (x > 0.f ? cv[q].y : cv[q].z);
                    acc[r][c] = fmaf(af[q], s, acc[r][c]);
                }
            }
        }
    }

#pragma unroll
    for (int r = 0; r < 4; r++) {
        float cv = cnt[r];
        for (int off = 16; off; off >>= 1) cv += __shfl_down_sync(0xffffffffu, cv, off);
#pragma unroll
        for (int c = 0; c < 6; c++) {
            float v = acc[r][c];
            for (int off = 16; off; off >>= 1) v += __shfl_down_sync(0xffffffffu, v, off);
            if (lane == 0) {
                float R = v + (2048.f - cv) * EXP30;
                float inv = 1.0f / R;
                g_row2[c * E + r0 + r] =
                    make_float4(e1[r][c], P1[r][c] * inv, N1[r][c] * inv, EXP30 * inv);
            }
        }
    }
}

// ---------------- K3: attention-weighted aggregation ----------------
__global__ void __launch_bounds__(256, 1) k3_att(const float* __restrict__ adj)
{
    int j0 = blockIdx.x * 512 + threadIdx.x * 2;
    int slab = blockIdx.y;

    float e2[2][6], P2[2][6], N2[2][6];
#pragma unroll
    for (int c = 0; c < 6; c++) {
        float4 v0 = g_colv[c * E + j0];
        float4 v1 = g_colv[c * E + j0 + 1];
        e2[0][c] = v0.x; P2[0][c] = v0.y; N2[0][c] = v0.z;
        e2[1][c] = v1.x; P2[1][c] = v1.y; N2[1][c] = v1.z;
    }

    float acc0[36], acc1[36];
#pragma unroll
    for (int q = 0; q < 36; q++) { acc0[q] = 0.f; acc1[q] = 0.f; }

    int i0 = slab * SLAB;
    int i1 = i0 + SLAB; if (i1 > E) i1 = E;
    for (int i = i0; i < i1; i++) {
        float2 av = *(const float2*)&adj[(size_t)i * E + j0];
#pragma unroll
        for (int c = 0; c < 6; c++) {
            float4 rv = g_row2[c * E + i];
            float4 hA = g_hA[c * E + i];
            float2 hB = g_hB[c * E + i];

            float x0 = rv.x + e2[0][c];
            float w0 = av.x * ((x0 > 0.f ? rv.y : rv.z) * (x0 > 0.f ? P2[0][c] : N2[0][c]));
            float x1 = rv.x + e2[1][c];
            float w1 = av.y * ((x1 > 0.f ? rv.y : rv.z) * (x1 > 0.f ? P2[1][c] : N2[1][c]));

            int b = c * 6;
            acc0[b + 0] = fmaf(w0, hA.x, acc0[b + 0]);
            acc0[b + 1] = fmaf(w0, hA.y, acc0[b + 1]);
            acc0[b + 2] = fmaf(w0, hA.z, acc0[b + 2]);
            acc0[b + 3] = fmaf(w0, hA.w, acc0[b + 3]);
            acc0[b + 4] = fmaf(w0, hB.x, acc0[b + 4]);
            acc0[b + 5] = fmaf(w0, hB.y, acc0[b + 5]);
            acc1[b + 0] = fmaf(w1, hA.x, acc1[b + 0]);
            acc1[b + 1] = fmaf(w1, hA.y, acc1[b + 1]);
            acc1[b + 2] = fmaf(w1, hA.z, acc1[b + 2]);
            acc1[b + 3] = fmaf(w1, hA.w, acc1[b + 3]);
            acc1[b + 4] = fmaf(w1, hB.x, acc1[b + 4]);
            acc1[b + 5] = fmaf(w1, hB.y, acc1[b + 5]);
        }
    }

    float* d0 = &g_part[((size_t)slab * E + j0) * 36];
    float* d1 = &g_part[((size_t)slab * E + j0 + 1) * 36];
#pragma unroll
    for (int q = 0; q < 9; q++) {
        ((float4*)d0)[q] = make_float4(acc0[4*q], acc0[4*q+1], acc0[4*q+2], acc0[4*q+3]);
        ((float4*)d1)[q] = make_float4(acc1[4*q], acc1[4*q+1], acc1[4*q+2], acc1[4*q+3]);
    }
}

// ---------------- K4: reduce slabs + ELU + head concat ----------------
__global__ void k4_reduce()
{
    int idx = blockIdx.x * 256 + threadIdx.x;   // < 2048*36
    int j = idx / 36, cd = idx % 36;
    float s = 0.f;
    for (int sl = 0; sl < NSLAB; sl++) s += g_part[((size_t)sl * E + j) * 36 + cd];
    float v = s > 0.f ? s : expm1f(s);
    int g = cd / 18;
    g_hcat[g * (E * 18) + j * 18 + (cd - g * 18)] = v;
}

// ---------------- K5: XW = [hcat_h @ Wg1 | hcat_o @ Wo1] ----------------
__global__ void k5_xw(const float* __restrict__ Wg1, const float* __restrict__ Wo1)
{
    int idx = blockIdx.x * 256 + threadIdx.x;   // 2048*32
    int j = idx >> 5, c = idx & 31;
    int g = c >> 4, cc = c & 15;
    const float* W = g ? Wo1 : Wg1;
    const float* h = &g_hcat[g * (E * 18) + j * 18];
    float s = 0.f;
#pragma unroll
    for (int k = 0; k < 18; k++) s = fmaf(h[k], W[k * 16 + cc], s);
    g_XW[idx] = s;
}

// ---------------- G1: a0 @ XW (tiled, k-split) ----------------
__global__ void __launch_bounds__(256) g1_gemm(const float* __restrict__ adj)
{
    __shared__ float As[64][33];
    __shared__ float Bs[32][32];
    int r0 = blockIdx.x * 64, k0 = blockIdx.y * 256;
    int rl = threadIdx.x >> 2, cg = (threadIdx.x & 3) * 8;
    int kc = threadIdx.x & 31, rr = threadIdx.x >> 5;

    float acc[8];
#pragma unroll
    for (int u = 0; u < 8; u++) acc[u] = 0.f;

    for (int kt = 0; kt < 8; kt++) {
        int kb = k0 + kt * 32;
#pragma unroll
        for (int p = 0; p < 8; p++)
            As[rr + p * 8][kc] = adj[(size_t)(r0 + rr + p * 8) * E + kb + kc];
#pragma unroll
        for (int p = 0; p < 4; p++)
            Bs[rr + p * 8][kc] = g_XW[(kb + rr + p * 8) * 32 + kc];
        __syncthreads();
#pragma unroll
        for (int kk = 0; kk < 32; kk++) {
            float a = As[rl][kk];
            const float4* b = (const float4*)&Bs[kk][cg];
            float4 b0 = b[0], b1 = b[1];
            acc[0] = fmaf(a, b0.x, acc[0]);
            acc[1] = fmaf(a, b0.y, acc[1]);
            acc[2] = fmaf(a, b0.z, acc[2]);
            acc[3] = fmaf(a, b0.w, acc[3]);
            acc[4] = fmaf(a, b1.x, acc[4]);
            acc[5] = fmaf(a, b1.y, acc[5]);
            acc[6] = fmaf(a, b1.z, acc[6]);
            acc[7] = fmaf(a, b1.w, acc[7]);
        }
        __syncthreads();
    }
    float* dst = &g_G1p[((size_t)blockIdx.y * E + r0 + rl) * 32 + cg];
    ((float4*)dst)[0] = make_float4(acc[0], acc[1], acc[2], acc[3]);
    ((float4*)dst)[1] = make_float4(acc[4], acc[5], acc[6], acc[7]);
}

// ---------------- G1r: reduce k-slices + bias + relu ----------------
__global__ void g1_reduce(const float* __restrict__ bg1, const float* __restrict__ bo1)
{
    int idx = blockIdx.x * 256 + threadIdx.x;   // 2048*32
    int c = idx & 31;
    float s = 0.f;
#pragma unroll
    for (int ks = 0; ks < 8; ks++) s += g_G1p[((size_t)ks * E) * 32 + idx];
    s += (c < 16) ? bg1[c] : bo1[c - 16];
    g_YO1[idx] = s > 0.f ? s : 0.f;
}

// ---------------- G2a: Z = [Y1@Wg2 | O1@Wo2] ----------------
__global__ void g2a(const float* __restrict__ Wg2, const float* __restrict__ Wo2)
{
    int j = blockIdx.x * 256 + threadIdx.x;     // 2048
    const float* y = &g_YO1[j * 32];
    float z0 = 0.f, z1 = 0.f, z2 = 0.f, z3 = 0.f;
#pragma unroll
    for (int k = 0; k < 16; k++) {
        z0 = fmaf(y[k], Wg2[k * 2 + 0], z0);
        z1 = fmaf(y[k], Wg2[k * 2 + 1], z1);
        z2 = fmaf(y[16 + k], Wo2[k * 2 + 0], z2);
        z3 = fmaf(y[16 + k], Wo2[k * 2 + 1], z3);
    }
    g_Z[j] = make_float4(z0, z1, z2, z3);
}

// ---------------- G2b: a0 @ Z + bias, log_softmax / leaky ----------------
__global__ void __launch_bounds__(256) g2b(const float* __restrict__ adj,
                                           const float* __restrict__ bg2,
                                           const float* __restrict__ bo2,
                                           float* __restrict__ out)
{
    int warp = threadIdx.x >> 5, lane = threadIdx.x & 31;
    int r = blockIdx.x * 8 + warp;
    float a0 = 0.f, a1 = 0.f, a2 = 0.f, a3 = 0.f;
    for (int q = 0; q < 64; q++) {
        int k = q * 32 + lane;
        float av = adj[(size_t)r * E + k];
        float4 z = g_Z[k];
        a0 = fmaf(av, z.x, a0);
        a1 = fmaf(av, z.y, a1);
        a2 = fmaf(av, z.z, a2);
        a3 = fmaf(av, z.w, a3);
    }
    for (int off = 16; off; off >>= 1) {
        a0 += __shfl_down_sync(0xffffffffu, a0, off);
        a1 += __shfl_down_sync(0xffffffffu, a1, off);
        a2 += __shfl_down_sync(0xffffffffu, a2, off);
        a3 += __shfl_down_sync(0xffffffffu, a3, off);
    }
    if (lane == 0) {
        float y0 = a0 + bg2[0], y1 = a1 + bg2[1];
        float m = fmaxf(y0, y1);
        float l = m + logf(expf(y0 - m) + expf(y1 - m));
        out[r * 2 + 0] = y0 - l;
        out[r * 2 + 1] = y1 - l;
        float o0 = a2 + bo2[0], o1 = a3 + bo2[1];
        out[2 * E + r * 2 + 0] = o0 > 0.f ? o0 : 0.01f * o0;
        out[2 * E + r * 2 + 1] = o1 > 0.f ? o1 : 0.01f * o1;
    }
}

// ---------------- launch ----------------
extern "C" void kernel_launch(void* const* d_in, const int* in_sizes, int n_in,
                              void* d_out, int out_size)
{
    (void)in_sizes; (void)n_in; (void)out_size;
    const float* node = (const float*)d_in[0];
    const float* uv   = (const float*)d_in[1];
    const float* adj  = (const float*)d_in[2];   // batch 0 = first E*E floats
    const float* Wt1  = (const float*)d_in[3];
    const float* at1  = (const float*)d_in[4];
    const float* Wt2  = (const float*)d_in[5];
    const float* at2  = (const float*)d_in[6];
    const float* Wg1  = (const float*)d_in[7];
    const float* bg1  = (const float*)d_in[8];
    const float* Wg2  = (const float*)d_in[9];
    const float* bg2  = (const float*)d_in[10];
    const float* Wo1  = (const float*)d_in[11];
    const float* bo1  = (const float*)d_in[12];
    const float* Wo2  = (const float*)d_in[13];
    const float* bo2  = (const float*)d_in[14];
    float* out = (float*)d_out;

    k1_prep<<<dim3(8, 6), 256>>>(node, uv, Wt1, at1, Wt2, at2);
    k2_rowsum<<<128, 128>>>(adj);
    k3_att<<<dim3(4, NSLAB), 256>>>(adj);
    k4_reduce<<<288, 256>>>();
    k5_xw<<<256, 256>>>(Wg1, Wo1);
    g1_gemm<<<dim3(32, 8), 256>>>(adj);
    g1_reduce<<<256, 256>>>(bg1, bo1);
    g2a<<<8, 256>>>(Wg2, Wo2);
    g2b<<<256, 256>>>(adj, bg2, bo2, out);
}